// round 2
// baseline (speedup 1.0000x reference)
#include <cuda_runtime.h>
#include <math_constants.h>

#define B_   32
#define N_   128
#define C_   25
#define NC   3200                       // N_*C_ candidates per center
#define S_   13107200                   // B_*N_*N_*C_ elements per output tensor
#define CAP  256
#define RAD2 64.0f
#define EPS2 1e-4f
#define NT   800                        // threads per block = NC/4
#define NW   25                         // warps per block

__global__ void zero_counts_kernel(float* __restrict__ out) {
    if (threadIdx.x < B_) out[(size_t)3 * S_ + threadIdx.x] = 0.0f;
}

// Block-wide int sum over 25 full warps.
__device__ __forceinline__ int block_reduce_add(int v, int tid, int* sred) {
    v = __reduce_add_sync(0xffffffffu, v);
    __syncthreads();                       // protect sred from previous use
    if ((tid & 31) == 0) sred[tid >> 5] = v;
    __syncthreads();
    if (tid < 32) {
        int x = (tid < NW) ? sred[tid] : 0;
        x = __reduce_add_sync(0xffffffffu, x);
        if (tid == 0) sred[0] = x;
    }
    __syncthreads();
    return sred[0];
}

__global__ __launch_bounds__(NT)
void pbc_graph_kernel(const float* __restrict__ pos,
                      const float* __restrict__ cell,
                      float* __restrict__ out) {
    const int center = blockIdx.x;       // b*128 + i
    const int b = center >> 7;
    const int i = center & 127;
    const int tid = threadIdx.x;

    __shared__ float4 srel[N_];          // pos[j] - pos[i]
    __shared__ float4 soff[C_];
    __shared__ int    sred[32];
    __shared__ int    s_n;
    __shared__ unsigned long long slist[CAP];
    __shared__ float  s_Tf;              // d2 of 32nd-smallest key (inf if <=32 within)
    __shared__ int    s_Tc;              // tie-break cand index of that key

    if (tid < N_) {
        const float* p = pos + (size_t)b * N_ * 3 + tid * 3;
        srel[tid] = make_float4(p[0], p[1], p[2], 0.0f);
    }
    if (tid >= N_ && tid < N_ + C_) {
        int c = tid - N_;
        float u0 = (float)(c / 5 - 2);
        float u1 = (float)(c % 5 - 2);
        const float* cb = cell + b * 9;
        soff[c] = make_float4(
            __fmaf_rn(u0, cb[0], __fmul_rn(u1, cb[3])),
            __fmaf_rn(u0, cb[1], __fmul_rn(u1, cb[4])),
            __fmaf_rn(u0, cb[2], __fmul_rn(u1, cb[5])), 0.0f);
    }
    if (tid == 0) { s_n = 0; s_Tf = CUDART_INF_F; s_Tc = -1; }
    __syncthreads();
    const float4 pi = srel[i];
    __syncthreads();
    if (tid < N_) {
        float4 v = srel[tid];
        srel[tid] = make_float4(__fsub_rn(v.x, pi.x),
                                __fsub_rn(v.y, pi.y),
                                __fsub_rn(v.z, pi.z), 0.0f);
    }
    __syncthreads();

    // ---- phase 1: d2 for 4 consecutive candidates, kept in registers ----
    const int cand0 = tid * 4;
    const int j0 = cand0 / 25;
    const int c0 = cand0 - j0 * 25;

    float d2r[4];
    int lw = 0;
    {
        int j = j0, c = c0;
#pragma unroll
        for (int q = 0; q < 4; q++) {
            float4 r = srel[j];
            float4 o = soff[c];
            float dx = __fadd_rn(r.x, o.x);     // == fadd(fsub(pj,pi), off)
            float dy = __fadd_rn(r.y, o.y);
            float dz = __fadd_rn(r.z, o.z);
            float d2 = __fmaf_rn(dx, dx, __fmaf_rn(dy, dy, __fmul_rn(dz, dz)));
            bool within = (d2 <= RAD2) && (d2 > EPS2);
            d2r[q] = within ? d2 : CUDART_INF_F;
            lw += within ? 1 : 0;
            if (++c == 25) { c = 0; ++j; }
        }
    }
    const int cntw = block_reduce_add(lw, tid, sred);

    // ---- phase 2: exact 32nd-smallest (d2, cand) via bisection + small-bin rank ----
    if (cntw > 32) {
        float lo = 0.0f, hi = RAD2;
        int cnt_lo = 0, cnt_hi = cntw;
        for (int iter = 0; iter < 48; iter++) {
            if (cnt_hi - cnt_lo <= CAP) break;
            float mid = 0.5f * (lo + hi);
            if (!(mid > lo && mid < hi)) break;   // float exhaustion guard
            int lc = 0;
#pragma unroll
            for (int q = 0; q < 4; q++) lc += (d2r[q] <= mid) ? 1 : 0;
            int cm = block_reduce_add(lc, tid, sred);
            if (cm >= 32) { hi = mid; cnt_hi = cm; }
            else          { lo = mid; cnt_lo = cm; }
        }

        // compact window (lo, hi] into shared keys
#pragma unroll
        for (int q = 0; q < 4; q++) {
            float d = d2r[q];
            if (d > lo && d <= hi) {
                int p = atomicAdd(&s_n, 1);
                if (p < CAP)
                    slist[p] = ((unsigned long long)__float_as_uint(d) << 12)
                             | (unsigned)(cand0 + q);
            }
        }
        __syncthreads();
        int n = min(s_n, CAP);
        int need = 32 - cnt_lo;                   // in [1, CAP]
        if (tid < n) {
            unsigned long long k = slist[tid];
            int r = 0;
            for (int m = 0; m < n; m++) r += (slist[m] < k) ? 1 : 0;
            if (r == need - 1) {                  // exact 32nd smallest key
                s_Tf = __uint_as_float((unsigned)(k >> 12));
                s_Tc = (int)(k & 0xFFFu);
            }
        }
        __syncthreads();
    }

    const float Tf = s_Tf;
    const int   Tc = s_Tc;

    // ---- phase 3: vectorized output writes ----
    float dist[4] = {0.f, 0.f, 0.f, 0.f};
    float ctf[4]  = {0.f, 0.f, 0.f, 0.f};
    float mk[4]   = {0.f, 0.f, 0.f, 0.f};
    {
        int c = c0;
#pragma unroll
        for (int q = 0; q < 4; q++) {
            float d = d2r[q];
            bool keep = (d < Tf) || ((d == Tf) && (cand0 + q <= Tc));
            if (keep) {                           // d finite => within
                dist[q] = sqrtf(d);
                ctf[q]  = (float)(5 * (c / 5 + c % 5));
                mk[q]   = 1.0f;
            }
            if (++c == 25) c = 0;
        }
    }

    const size_t base4 = ((size_t)center * NC) / 4 + (size_t)tid;
    float4* o0 = (float4*)out;
    float4* o1 = (float4*)(out + (size_t)S_);
    float4* o2 = (float4*)(out + (size_t)2 * S_);
    o0[base4] = make_float4(dist[0], dist[1], dist[2], dist[3]);
    o1[base4] = make_float4(ctf[0],  ctf[1],  ctf[2],  ctf[3]);
    o2[base4] = make_float4(mk[0],   mk[1],   mk[2],   mk[3]);

    if (tid == 0)
        atomicAdd(&out[(size_t)3 * S_ + b], (float)(cntw < 32 ? cntw : 32));
}

extern "C" void kernel_launch(void* const* d_in, const int* in_sizes, int n_in,
                              void* d_out, int out_size) {
    const float* pos;
    const float* cell;
    if (n_in >= 2 && in_sizes[0] == B_ * N_ * 3) {
        pos  = (const float*)d_in[0];
        cell = (const float*)d_in[1];
    } else {
        pos  = (const float*)d_in[1];
        cell = (const float*)d_in[0];
    }
    float* out = (float*)d_out;

    zero_counts_kernel<<<1, 32>>>(out);
    pbc_graph_kernel<<<B_ * N_, NT>>>(pos, cell, out);
}

// round 3
// speedup vs baseline: 1.5466x; 1.5466x over previous
#include <cuda_runtime.h>
#include <math_constants.h>

#define B_    32
#define N_    128
#define C_    25
#define NC    3200                      // N_*C_ candidates per center
#define S_    13107200                  // B_*N_*N_*C_ elements per output tensor
#define RAD2  64.0f
#define EPS2  1e-4f
#define NT    256                       // threads per block (200 active workers)
#define PT    16                        // candidates per worker thread
#define NACT  200                       // active workers: 200*16 = 3200
#define NBIN  256
#define CAP   256

__global__ void zero_counts_kernel(float* __restrict__ out) {
    if (threadIdx.x < B_) out[(size_t)3 * S_ + threadIdx.x] = 0.0f;
}

__global__ __launch_bounds__(NT)
void pbc_graph_kernel(const float* __restrict__ pos,
                      const float* __restrict__ cell,
                      float* __restrict__ out) {
    const int center = blockIdx.x;      // b*128 + i
    const int b = center >> 7;
    const int i = center & 127;
    const int tid = threadIdx.x;

    __shared__ float4 spos4[N_];
    __shared__ float4 soff[C_];
    __shared__ float  sctf[C_];
    __shared__ int    hist[NBIN];
    __shared__ int    s_n, s_t, s_cntlo, s_total;
    __shared__ unsigned long long slist[CAP];
    __shared__ float  s_Tf;             // 32nd-smallest d2 (inf if <=32 within)
    __shared__ int    s_Tc;             // tie-break cand of that key

    // ---- setup ----
    if (tid < N_) {
        const float* p = pos + (size_t)b * N_ * 3 + tid * 3;
        spos4[tid] = make_float4(p[0], p[1], p[2], 0.0f);
    }
    if (tid >= N_ && tid < N_ + C_) {
        int c = tid - N_;
        float u0 = (float)(c / 5 - 2);
        float u1 = (float)(c % 5 - 2);
        const float* cb = cell + b * 9;
        soff[c] = make_float4(
            __fmaf_rn(u0, cb[0], __fmul_rn(u1, cb[3])),
            __fmaf_rn(u0, cb[1], __fmul_rn(u1, cb[4])),
            __fmaf_rn(u0, cb[2], __fmul_rn(u1, cb[5])), 0.0f);
        sctf[c] = (float)(5 * (c / 5 + c % 5));
    }
    hist[tid] = 0;
    if (tid == 0) { s_n = 0; s_t = -1; s_Tf = CUDART_INF_F; s_Tc = -1; }
    __syncthreads();                                            // B1

    const float4 pi = spos4[i];

    // ---- phase 1: d2 for 16 consecutive candidates, registers only ----
    float d2r[PT];
    const int cand0 = tid * PT;
    if (tid < NACT) {
        int j = cand0 / 25;
        int c = cand0 - j * 25;
        float4 rj = spos4[j];
        float rx = __fsub_rn(rj.x, pi.x);
        float ry = __fsub_rn(rj.y, pi.y);
        float rz = __fsub_rn(rj.z, pi.z);
#pragma unroll
        for (int q = 0; q < PT; q++) {
            float4 o = soff[c];
            float dx = __fadd_rn(rx, o.x);
            float dy = __fadd_rn(ry, o.y);
            float dz = __fadd_rn(rz, o.z);
            float d2 = __fmaf_rn(dx, dx, __fmaf_rn(dy, dy, __fmul_rn(dz, dz)));
            bool within = (d2 <= RAD2) && (d2 > EPS2);
            d2r[q] = within ? d2 : CUDART_INF_F;
            if (within) {
                int bin = min((int)(d2 * 4.0f), NBIN - 1);
                atomicAdd(&hist[bin], 1);
            }
            if (++c == 25) {
                c = 0;
                j = min(j + 1, N_ - 1);     // guard; reload unused past end
                rj = spos4[j];
                rx = __fsub_rn(rj.x, pi.x);
                ry = __fsub_rn(rj.y, pi.y);
                rz = __fsub_rn(rj.z, pi.z);
            }
        }
    }
    __syncthreads();                                            // B2

    // ---- phase 2a: warp 0 scans histogram, finds bin holding rank 32 ----
    if (tid < 32) {
        int loc[8], sum = 0;
#pragma unroll
        for (int k = 0; k < 8; k++) { loc[k] = hist[tid * 8 + k]; sum += loc[k]; }
        // exclusive scan of chunk sums across lanes
        int pre = sum;
#pragma unroll
        for (int d = 1; d < 32; d <<= 1) {
            int v = __shfl_up_sync(0xffffffffu, pre, d);
            if ((tid & 31) >= d) pre += v;
        }
        int total = __shfl_sync(0xffffffffu, pre, 31);
        pre -= sum;                          // exclusive prefix
        if (tid == 0) s_total = total;
        if (total > 32 && pre < 32 && 32 <= pre + sum) {
            int cum = pre;
#pragma unroll
            for (int k = 0; k < 8; k++) {
                if (cum < 32 && cum + loc[k] >= 32) { s_t = tid * 8 + k; s_cntlo = cum; }
                cum += loc[k];
            }
        }
    }
    __syncthreads();                                            // B3

    const int cntw = s_total;
    const int tbin = s_t;

    // ---- phase 2b: compact boundary bin, exact rank ----
    if (cntw > 32) {
        if (tid < NACT) {
#pragma unroll
            for (int q = 0; q < PT; q++) {
                float d = d2r[q];
                if (d <= RAD2 && min((int)(d * 4.0f), NBIN - 1) == tbin) {
                    int p = atomicAdd(&s_n, 1);
                    if (p < CAP)
                        slist[p] = ((unsigned long long)__float_as_uint(d) << 12)
                                 | (unsigned)(cand0 + q);
                }
            }
        }
        __syncthreads();                                        // B4
        int n = min(s_n, CAP);
        int need = 32 - s_cntlo;             // in [1, n]
        if (tid < n) {
            unsigned long long k = slist[tid];
            int r = 0;
            for (int m = 0; m < n; m++) r += (slist[m] < k) ? 1 : 0;
            if (r == need - 1) {             // exact 32nd smallest key
                s_Tf = __uint_as_float((unsigned)(k >> 12));
                s_Tc = (int)(k & 0xFFFu);
            }
        }
        __syncthreads();                                        // B5
    }

    const float Tf = s_Tf;
    const int   Tc = s_Tc;

    // ---- phase 3: vectorized output writes ----
    if (tid < NACT) {
        float dist[PT], ctf[PT], mk[PT];
        int c = cand0 - (cand0 / 25) * 25;
#pragma unroll
        for (int q = 0; q < PT; q++) {
            float d = d2r[q];
            bool keep = (d < Tf) || ((d == Tf) && (cand0 + q <= Tc));
            dist[q] = keep ? sqrtf(d) : 0.0f;
            ctf[q]  = keep ? sctf[c] : 0.0f;
            mk[q]   = keep ? 1.0f : 0.0f;
            if (++c == 25) c = 0;
        }
        const size_t base4 = ((size_t)center * NC + (size_t)cand0) >> 2;
        float4* o0 = (float4*)out;
        float4* o1 = (float4*)(out + (size_t)S_);
        float4* o2 = (float4*)(out + (size_t)2 * S_);
#pragma unroll
        for (int v = 0; v < PT / 4; v++) {
            o0[base4 + v] = make_float4(dist[4*v], dist[4*v+1], dist[4*v+2], dist[4*v+3]);
            o1[base4 + v] = make_float4(ctf[4*v],  ctf[4*v+1],  ctf[4*v+2],  ctf[4*v+3]);
            o2[base4 + v] = make_float4(mk[4*v],   mk[4*v+1],   mk[4*v+2],   mk[4*v+3]);
        }
    }

    if (tid == 0)
        atomicAdd(&out[(size_t)3 * S_ + b], (float)(cntw < 32 ? cntw : 32));
}

extern "C" void kernel_launch(void* const* d_in, const int* in_sizes, int n_in,
                              void* d_out, int out_size) {
    const float* pos;
    const float* cell;
    if (n_in >= 2 && in_sizes[0] == B_ * N_ * 3) {
        pos  = (const float*)d_in[0];
        cell = (const float*)d_in[1];
    } else {
        pos  = (const float*)d_in[1];
        cell = (const float*)d_in[0];
    }
    float* out = (float*)d_out;

    zero_counts_kernel<<<1, 32>>>(out);
    pbc_graph_kernel<<<B_ * N_, NT>>>(pos, cell, out);
}

// round 5
// speedup vs baseline: 2.9337x; 1.8969x over previous
#include <cuda_runtime.h>
#include <math_constants.h>

#define B_    32
#define N_    128
#define C_    25
#define NC    3200                      // N_*C_ candidates per center
#define S_    13107200                  // B_*N_*N_*C_ elements per output tensor
#define RAD2  64.0f
#define EPS2  1e-4f
#define NT    256
#define NBIN  256
#define CAP   128
#define PREF  8.0f                      // prefilter bound for fine histogram

__global__ void zero_counts_kernel(float* __restrict__ out) {
    if (threadIdx.x < B_) out[(size_t)3 * S_ + threadIdx.x] = 0.0f;
}

__global__ __launch_bounds__(NT)
void pbc_graph_kernel(const float* __restrict__ pos,
                      const float* __restrict__ cell,
                      float* __restrict__ out) {
    const int center = blockIdx.x;      // b*128 + i
    const int b = center >> 7;
    const int i = center & 127;
    const int tid = threadIdx.x;

    __shared__ float4 spos4[N_];
    __shared__ float4 soff[C_];
    __shared__ __align__(16) float sdist[NC];   // d2 or +inf (16B for LDS.128)
    __shared__ float  sctf[C_];
    __shared__ int    hist[NBIN];
    __shared__ int    s_n, s_t, s_cntlo, s_total;
    __shared__ unsigned long long slist[CAP];
    __shared__ float  s_Tf;
    __shared__ int    s_Tc;

    // ---- setup ----
    if (tid < N_) {
        const float* p = pos + (size_t)b * N_ * 3 + tid * 3;
        spos4[tid] = make_float4(p[0], p[1], p[2], 0.0f);
    }
    if (tid >= N_ && tid < N_ + C_) {
        int c = tid - N_;
        float u0 = (float)(c / 5 - 2);
        float u1 = (float)(c % 5 - 2);
        const float* cb = cell + b * 9;
        soff[c] = make_float4(
            __fmaf_rn(u0, cb[0], __fmul_rn(u1, cb[3])),
            __fmaf_rn(u0, cb[1], __fmul_rn(u1, cb[4])),
            __fmaf_rn(u0, cb[2], __fmul_rn(u1, cb[5])), 0.0f);
        sctf[c] = (float)(5 * (c / 5 + c % 5));
    }
    hist[tid] = 0;
    if (tid == 0) { s_n = 0; s_t = -1; s_cntlo = 0; s_Tf = CUDART_INF_F; s_Tc = -1; }
    __syncthreads();                                            // B1

    const float4 pi = spos4[i];

    // ---- phase 1: thread = (j, half); broadcast soff; fine histogram d2<8 ----
    const int j    = tid >> 1;
    const int half = tid & 1;
    const int cbeg = half ? 13 : 0;
    const int cend = half ? 25 : 13;
    const int jbase = j * 25;
    {
        float4 rj = spos4[j];
        float rx = __fsub_rn(rj.x, pi.x);
        float ry = __fsub_rn(rj.y, pi.y);
        float rz = __fsub_rn(rj.z, pi.z);
        for (int c = cbeg; c < cend; c++) {
            float4 o = soff[c];
            float dx = __fadd_rn(rx, o.x);
            float dy = __fadd_rn(ry, o.y);
            float dz = __fadd_rn(rz, o.z);
            float d2 = __fmaf_rn(dx, dx, __fmaf_rn(dy, dy, __fmul_rn(dz, dz)));
            bool within = (d2 <= RAD2) && (d2 > EPS2);
            sdist[jbase + c] = within ? d2 : CUDART_INF_F;
            if (within && d2 < PREF)
                atomicAdd(&hist[(int)(d2 * 32.0f)], 1);
        }
    }

    // ---- phase 2: selection (fine pass; full-range fallback if needed) ----
    float scale = 32.0f;
    float bound = PREF;
    for (int pass = 0; ; pass++) {
        __syncthreads();                                        // hist ready
        if (tid < 32) {                 // warp-0 scan of 256 bins
            int loc[8], sum = 0;
#pragma unroll
            for (int k = 0; k < 8; k++) { loc[k] = hist[tid * 8 + k]; sum += loc[k]; }
            int pre = sum;
#pragma unroll
            for (int d = 1; d < 32; d <<= 1) {
                int v = __shfl_up_sync(0xffffffffu, pre, d);
                if (tid >= d) pre += v;
            }
            int total = __shfl_sync(0xffffffffu, pre, 31);
            pre -= sum;
            if (tid == 0) s_total = total;
            if (total > 32 && pre < 32 && 32 <= pre + sum) {
                int cum = pre;
#pragma unroll
                for (int k = 0; k < 8; k++) {
                    if (cum < 32 && cum + loc[k] >= 32) { s_t = tid * 8 + k; s_cntlo = cum; }
                    cum += loc[k];
                }
            }
        }
        __syncthreads();
        if (s_total >= 32 || pass == 1) break;
        // fallback: rebuild over full range from sdist (rare)
        hist[tid] = 0;
        __syncthreads();
        scale = 4.0f; bound = CUDART_INF_F;
        for (int c = cbeg; c < cend; c++) {
            float d = sdist[jbase + c];
            if (d <= RAD2)
                atomicAdd(&hist[min((int)(d * 4.0f), NBIN - 1)], 1);
        }
    }

    const int total = s_total;
    if (total > 32) {
        // compact boundary bin, exact rank with stable (d2, cand) key
        const int tbin = s_t;
        for (int c = cbeg; c < cend; c++) {
            float d = sdist[jbase + c];
            if (d < bound && min((int)(d * scale), NBIN - 1) == tbin) {
                int p = atomicAdd(&s_n, 1);
                if (p < CAP)
                    slist[p] = ((unsigned long long)__float_as_uint(d) << 12)
                             | (unsigned)(jbase + c);
            }
        }
        __syncthreads();                                        // B4
        int n = min(s_n, CAP);
        int need = 32 - s_cntlo;
        if (tid < n) {
            unsigned long long k = slist[tid];
            int r = 0;
            for (int m = 0; m < n; m++) r += (slist[m] < k) ? 1 : 0;
            if (r == need - 1) {
                s_Tf = __uint_as_float((unsigned)(k >> 12));
                s_Tc = (int)(k & 0xFFFu);
            }
        }
        __syncthreads();                                        // B5
    } else {
        if (tid == 0) { s_Tf = bound; s_Tc = -1; }  // keep all hist-covered
        __syncthreads();
    }

    const float Tf = s_Tf;
    const int   Tc = s_Tc;

    // ---- phase 3: vectorized read-back + STG.128 writes ----
    const float4* sd4 = (const float4*)sdist;
    float4* o0 = (float4*)out                    + ((size_t)center * NC >> 2);
    float4* o1 = (float4*)(out + (size_t)S_)     + ((size_t)center * NC >> 2);
    float4* o2 = (float4*)(out + (size_t)2 * S_) + ((size_t)center * NC >> 2);
#pragma unroll
    for (int v = tid; v < NC / 4; v += NT) {
        float4 dv = sd4[v];
        int cand = 4 * v;
        bool k0 = (dv.x < Tf) || (dv.x == Tf && cand     <= Tc);
        bool k1 = (dv.y < Tf) || (dv.y == Tf && cand + 1 <= Tc);
        bool k2 = (dv.z < Tf) || (dv.z == Tf && cand + 2 <= Tc);
        bool k3 = (dv.w < Tf) || (dv.w == Tf && cand + 3 <= Tc);
        float4 od = make_float4(0.f, 0.f, 0.f, 0.f);
        float4 oc = make_float4(0.f, 0.f, 0.f, 0.f);
        float4 om = make_float4(0.f, 0.f, 0.f, 0.f);
        if (k0 | k1 | k2 | k3) {        // rare branch: sqrt/LUT only here
            int c = cand % 25;
            int c1 = c + 1 == 25 ? 0 : c + 1;
            int c2 = c1 + 1 == 25 ? 0 : c1 + 1;
            int c3 = c2 + 1 == 25 ? 0 : c2 + 1;
            if (k0) { od.x = sqrtf(dv.x); oc.x = sctf[c];  om.x = 1.f; }
            if (k1) { od.y = sqrtf(dv.y); oc.y = sctf[c1]; om.y = 1.f; }
            if (k2) { od.z = sqrtf(dv.z); oc.z = sctf[c2]; om.z = 1.f; }
            if (k3) { od.w = sqrtf(dv.w); oc.w = sctf[c3]; om.w = 1.f; }
        }
        o0[v] = od;
        o1[v] = oc;
        o2[v] = om;
    }

    if (tid == 0) {
        float contrib = (bound == PREF) ? 32.0f : (float)(total < 32 ? total : 32);
        atomicAdd(&out[(size_t)3 * S_ + b], contrib);
    }
}

extern "C" void kernel_launch(void* const* d_in, const int* in_sizes, int n_in,
                              void* d_out, int out_size) {
    const float* pos;
    const float* cell;
    if (n_in >= 2 && in_sizes[0] == B_ * N_ * 3) {
        pos  = (const float*)d_in[0];
        cell = (const float*)d_in[1];
    } else {
        pos  = (const float*)d_in[1];
        cell = (const float*)d_in[0];
    }
    float* out = (float*)d_out;

    zero_counts_kernel<<<1, 32>>>(out);
    pbc_graph_kernel<<<B_ * N_, NT>>>(pos, cell, out);
}